// round 1
// baseline (speedup 1.0000x reference)
#include <cuda_runtime.h>
#include <math.h>

// Problem constants
#define SEQ   4096
#define BATCH 2
#define HID   2048
#define NHEADS 16
#define NKVH   4
#define HDIM   128
#define ROWS  (BATCH*SEQ)          // 8192
#define GRPSZ 1024
#define NGRP  4

// Scratch (no cudaMalloc allowed)
__device__ float g_Q[ROWS*HID];            // (row, h*128+d)  64MB
__device__ float g_K[ROWS*NKVH*HDIM];      // (row, kvh*128+d) 16MB
__device__ float g_V[ROWS*NKVH*HDIM];      // 16MB
__device__ float g_C[ROWS*HID];            // attention context 64MB

// ---------------------------------------------------------------------------
// Generic fp32 SGEMM: C[M,N] = A[M,K] @ B[K,N], all row-major.
// M%128==0, N%128==0, K%16==0 guaranteed by problem shapes.
// ---------------------------------------------------------------------------
__global__ void __launch_bounds__(256) sgemm128(const float* __restrict__ A,
                                                const float* __restrict__ B,
                                                float* __restrict__ C,
                                                int M, int N, int K) {
    __shared__ float As[16][132];   // transposed A tile, +4 pad
    __shared__ float Bs[16][128];
    const int tid = threadIdx.x;
    const int tx = tid & 15, ty = tid >> 4;
    const float* Ablk = A + (size_t)blockIdx.x * 128 * K;
    const float* Bblk = B + (size_t)blockIdx.y * 128;

    float acc[8][8];
#pragma unroll
    for (int i = 0; i < 8; i++)
#pragma unroll
        for (int j = 0; j < 8; j++) acc[i][j] = 0.f;

    for (int k0 = 0; k0 < K; k0 += 16) {
#pragma unroll
        for (int l = 0; l < 2; l++) {
            int fid = tid + l * 256;            // 512 float4s of A tile
            int row = fid >> 2;
            int kk  = (fid & 3) * 4;
            float4 v = *(const float4*)(Ablk + (size_t)row * K + k0 + kk);
            As[kk + 0][row] = v.x; As[kk + 1][row] = v.y;
            As[kk + 2][row] = v.z; As[kk + 3][row] = v.w;
        }
#pragma unroll
        for (int l = 0; l < 2; l++) {
            int fid = tid + l * 256;            // 512 float4s of B tile
            int kk = fid >> 5;
            int n4 = (fid & 31) * 4;
            *(float4*)&Bs[kk][n4] = *(const float4*)(Bblk + (size_t)(k0 + kk) * N + n4);
        }
        __syncthreads();
#pragma unroll
        for (int kk = 0; kk < 16; kk++) {
            float a[8], b[8];
            *(float4*)&a[0] = *(const float4*)&As[kk][ty * 8];
            *(float4*)&a[4] = *(const float4*)&As[kk][ty * 8 + 4];
            *(float4*)&b[0] = *(const float4*)&Bs[kk][tx * 8];
            *(float4*)&b[4] = *(const float4*)&Bs[kk][tx * 8 + 4];
#pragma unroll
            for (int i = 0; i < 8; i++)
#pragma unroll
                for (int j = 0; j < 8; j++)
                    acc[i][j] = fmaf(a[i], b[j], acc[i][j]);
        }
        __syncthreads();
    }
    float* Cp = C + (size_t)(blockIdx.x * 128 + ty * 8) * N + blockIdx.y * 128 + tx * 8;
#pragma unroll
    for (int i = 0; i < 8; i++) {
        *(float4*)(Cp + (size_t)i * N)     = make_float4(acc[i][0], acc[i][1], acc[i][2], acc[i][3]);
        *(float4*)(Cp + (size_t)i * N + 4) = make_float4(acc[i][4], acc[i][5], acc[i][6], acc[i][7]);
    }
}

// ---------------------------------------------------------------------------
// RoPE in-place on g_Q (16 heads) and g_K (4 kv heads).
// One warp per (row, head); lane handles freq j = lane and lane+32.
// Angle computed in double, reduced mod 2pi, then sincosf.
// ---------------------------------------------------------------------------
__global__ void __launch_bounds__(256) rope_kernel(const int* __restrict__ pos_ids) {
    __shared__ double invs[64];
    if (threadIdx.x < 64)
        // inv_freq[j] = 10000^(-2j/128) = 2^(-j * log2(10000)/64)
        invs[threadIdx.x] = exp2(-(double)threadIdx.x * (13.287712379549449 / 64.0));
    __syncthreads();

    int gwarp = (blockIdx.x * blockDim.x + threadIdx.x) >> 5;   // 0..163839
    int lane  = threadIdx.x & 31;
    if (gwarp >= ROWS * (NHEADS + NKVH)) return;
    int h   = gwarp % (NHEADS + NKVH);
    int row = gwarp / (NHEADS + NKVH);
    float* p = (h < NHEADS) ? (g_Q + (size_t)row * HID + h * HDIM)
                            : (g_K + (size_t)row * (NKVH * HDIM) + (h - NHEADS) * HDIM);
    int ps = pos_ids[row];
    const double TWO_PI  = 6.283185307179586;
    const double INV_2PI = 0.15915494309189535;
#pragma unroll
    for (int jj = 0; jj < 2; jj++) {
        int j = lane + jj * 32;
        double ang = (double)ps * invs[j];
        ang -= floor(ang * INV_2PI) * TWO_PI;
        float s, c;
        sincosf((float)ang, &s, &c);
        float x0 = p[j], x1 = p[j + 64];
        p[j]      = x0 * c - x1 * s;
        p[j + 64] = x1 * c + x0 * s;
    }
}

// ---------------------------------------------------------------------------
// Flash-style grouped causal attention, fp32.
// grid = (16 q-tiles of 64 rows, 16 heads, 8 groups=B*ng). block = 256.
// Heads >= 8 use the S2-Attn shift: seq index = (base + t + 512) & 4095.
// ---------------------------------------------------------------------------
#define ATT_SMEM ((64*128 + 64*132 + 64*128 + 64*64) * 4)   // 115712 bytes

__global__ void __launch_bounds__(256) attn_kernel() {
    extern __shared__ float sm[];
    float* Qs = sm;                 // [64][128]
    float* Ks = Qs + 64 * 128;      // [64][132] padded
    float* Vs = Ks + 64 * 132;      // [64][128]
    float* Ps = Vs + 64 * 128;      // [64][64]

    const int qt = blockIdx.x;      // q tile within group (16)
    const int h  = blockIdx.y;      // head (16)
    const int gi = blockIdx.z;      // group (8) = b*4 + grp
    const int b = gi >> 2, grp = gi & 3;
    const int kvh = h >> 2;
    const int shift = (h >= NHEADS / 2) ? (GRPSZ / 2) : 0;
    const int base = grp * GRPSZ + shift;
    const int tid = threadIdx.x, tx = tid & 15, ty = tid >> 4;

    // Load Q tile (coalesced)
#pragma unroll
    for (int l = 0; l < 8; l++) {
        int fid = tid + l * 256;
        int r = fid >> 5, d4 = (fid & 31) * 4;
        int srow = b * SEQ + ((base + qt * 64 + r) & (SEQ - 1));
        *(float4*)&Qs[r * 128 + d4] = *(const float4*)&g_Q[(size_t)srow * HID + h * HDIM + d4];
    }

    float m[4], lsum[4], O[4][8];
#pragma unroll
    for (int r = 0; r < 4; r++) {
        m[r] = -1e30f; lsum[r] = 0.f;
#pragma unroll
        for (int c = 0; c < 8; c++) O[r][c] = 0.f;
    }

    const float SC = 0.08838834764831845f;  // 1/sqrt(128)
    const unsigned FULL = 0xffffffffu;

    for (int kt = 0; kt <= qt; kt++) {
        // Load K and V tiles
#pragma unroll
        for (int l = 0; l < 8; l++) {
            int fid = tid + l * 256;
            int r = fid >> 5, d4 = (fid & 31) * 4;
            int srow = b * SEQ + ((base + kt * 64 + r) & (SEQ - 1));
            size_t off = (size_t)srow * (NKVH * HDIM) + kvh * HDIM + d4;
            *(float4*)&Ks[r * 132 + d4] = *(const float4*)&g_K[off];
            *(float4*)&Vs[r * 128 + d4] = *(const float4*)&g_V[off];
        }
        __syncthreads();

        // S = Q K^T : rows ty*4+r, cols tx + 16*c
        float s[4][4];
#pragma unroll
        for (int r = 0; r < 4; r++)
#pragma unroll
            for (int c = 0; c < 4; c++) s[r][c] = 0.f;

#pragma unroll 8
        for (int k4 = 0; k4 < 32; k4++) {
            float4 qv[4], kv[4];
#pragma unroll
            for (int r = 0; r < 4; r++)
                qv[r] = *(const float4*)&Qs[(ty * 4 + r) * 128 + k4 * 4];
#pragma unroll
            for (int c = 0; c < 4; c++)
                kv[c] = *(const float4*)&Ks[(tx + 16 * c) * 132 + k4 * 4];
#pragma unroll
            for (int r = 0; r < 4; r++)
#pragma unroll
                for (int c = 0; c < 4; c++) {
                    s[r][c] = fmaf(qv[r].x, kv[c].x, s[r][c]);
                    s[r][c] = fmaf(qv[r].y, kv[c].y, s[r][c]);
                    s[r][c] = fmaf(qv[r].z, kv[c].z, s[r][c]);
                    s[r][c] = fmaf(qv[r].w, kv[c].w, s[r][c]);
                }
        }

        const bool diag = (kt == qt);
#pragma unroll
        for (int r = 0; r < 4; r++) {
#pragma unroll
            for (int c = 0; c < 4; c++) {
                float sv = s[r][c] * SC;
                if (diag && (tx + 16 * c) > (ty * 4 + r)) sv = -1e30f;
                s[r][c] = sv;
            }
            float mx = fmaxf(fmaxf(s[r][0], s[r][1]), fmaxf(s[r][2], s[r][3]));
#pragma unroll
            for (int o = 1; o < 16; o <<= 1)
                mx = fmaxf(mx, __shfl_xor_sync(FULL, mx, o));
            float mnew = fmaxf(m[r], mx);
            float corr = __expf(m[r] - mnew);
            float psum = 0.f;
#pragma unroll
            for (int c = 0; c < 4; c++) {
                float p = __expf(s[r][c] - mnew);
                Ps[(ty * 4 + r) * 64 + tx + 16 * c] = p;
                psum += p;
            }
#pragma unroll
            for (int o = 1; o < 16; o <<= 1)
                psum += __shfl_xor_sync(FULL, psum, o);
            lsum[r] = lsum[r] * corr + psum;
            m[r] = mnew;
#pragma unroll
            for (int c = 0; c < 8; c++) O[r][c] *= corr;
        }
        __syncwarp();

        // O += P @ V : rows ty*4+r, cols tx*8..tx*8+7
#pragma unroll 4
        for (int k = 0; k < 64; k++) {
            float4 v0 = *(const float4*)&Vs[k * 128 + tx * 8];
            float4 v1 = *(const float4*)&Vs[k * 128 + tx * 8 + 4];
#pragma unroll
            for (int r = 0; r < 4; r++) {
                float p = Ps[(ty * 4 + r) * 64 + k];
                O[r][0] = fmaf(p, v0.x, O[r][0]);
                O[r][1] = fmaf(p, v0.y, O[r][1]);
                O[r][2] = fmaf(p, v0.z, O[r][2]);
                O[r][3] = fmaf(p, v0.w, O[r][3]);
                O[r][4] = fmaf(p, v1.x, O[r][4]);
                O[r][5] = fmaf(p, v1.y, O[r][5]);
                O[r][6] = fmaf(p, v1.z, O[r][6]);
                O[r][7] = fmaf(p, v1.w, O[r][7]);
            }
        }
        __syncthreads();
    }

    // Epilogue: normalize and write to context at the un-shifted position
#pragma unroll
    for (int r = 0; r < 4; r++) {
        float inv = 1.f / lsum[r];
        int t = qt * 64 + ty * 4 + r;
        int srow = b * SEQ + ((base + t) & (SEQ - 1));
        float* o = &g_C[(size_t)srow * HID + h * HDIM + tx * 8];
        *(float4*)o       = make_float4(O[r][0] * inv, O[r][1] * inv, O[r][2] * inv, O[r][3] * inv);
        *(float4*)(o + 4) = make_float4(O[r][4] * inv, O[r][5] * inv, O[r][6] * inv, O[r][7] * inv);
    }
}

// ---------------------------------------------------------------------------
extern "C" void kernel_launch(void* const* d_in, const int* in_sizes, int n_in,
                              void* d_out, int out_size) {
    const float* X   = (const float*)d_in[0];   // hidden_states (2,4096,2048)
    // d_in[1] = attention_mask (exactly causal; implemented directly)
    const int*   pos = (const int*)d_in[2];     // position_ids (2,4096)
    const float* Wq  = (const float*)d_in[3];   // (2048, 2048)
    const float* Wk  = (const float*)d_in[4];   // (2048, 512)
    const float* Wv  = (const float*)d_in[5];   // (2048, 512)
    const float* Wo  = (const float*)d_in[6];   // (2048, 2048)
    float* out = (float*)d_out;

    float *Qb, *Kb, *Vb, *Cb;
    cudaGetSymbolAddress((void**)&Qb, g_Q);
    cudaGetSymbolAddress((void**)&Kb, g_K);
    cudaGetSymbolAddress((void**)&Vb, g_V);
    cudaGetSymbolAddress((void**)&Cb, g_C);

    cudaFuncSetAttribute(attn_kernel, cudaFuncAttributeMaxDynamicSharedMemorySize, ATT_SMEM);

    // QKV projections
    sgemm128<<<dim3(64, 16), 256>>>(X, Wq, Qb, ROWS, HID, HID);
    sgemm128<<<dim3(64, 4),  256>>>(X, Wk, Kb, ROWS, NKVH * HDIM, HID);
    sgemm128<<<dim3(64, 4),  256>>>(X, Wv, Vb, ROWS, NKVH * HDIM, HID);

    // RoPE on Q and K
    rope_kernel<<<20480, 256>>>(pos);

    // Grouped shifted causal attention
    attn_kernel<<<dim3(16, 16, 8), 256, ATT_SMEM>>>();

    // Output projection
    sgemm128<<<dim3(64, 16), 256>>>(Cb, Wo, out, ROWS, HID, HID);
}

// round 10
// speedup vs baseline: 2.0569x; 2.0569x over previous
#include <cuda_runtime.h>
#include <math.h>
#include <stdint.h>

// Problem constants
#define SEQ   4096
#define BATCH 2
#define HID   2048
#define NHEADS 16
#define NKVH   4
#define HDIM   128
#define ROWS  (BATCH*SEQ)          // 8192
#define GRPSZ 1024
#define NGRP  4

// Scratch (no cudaMalloc allowed)
__device__ float g_Q[ROWS*HID];            // 64MB
__device__ float g_K[ROWS*NKVH*HDIM];      // 16MB
__device__ float g_V[ROWS*NKVH*HDIM];      // 16MB
__device__ float g_C[ROWS*HID];            // 64MB attention context (tf32-rounded)
__device__ float g_Xr[ROWS*HID];           // 64MB tf32-rounded hidden states
__device__ float g_Wq[HID*HID];            // rounded weights, original [K,N] layout
__device__ float g_Wk[HID*(NKVH*HDIM)];
__device__ float g_Wv[HID*(NKVH*HDIM)];
__device__ float g_Wo[HID*HID];

// ---------------------------------------------------------------------------
// Helpers
// ---------------------------------------------------------------------------
__device__ __forceinline__ uint32_t smem_u32(const void* p) {
    uint32_t a;
    asm("{ .reg .u64 t; cvta.to.shared.u64 t, %1; cvt.u32.u64 %0, t; }" : "=r"(a) : "l"(p));
    return a;
}
__device__ __forceinline__ float round_tf32(float x) {
    uint32_t u;
    asm("cvt.rna.tf32.f32 %0, %1;" : "=r"(u) : "f"(x));
    return __uint_as_float(u);
}
__device__ __forceinline__ void cp16(uint32_t dst, const void* src) {
    asm volatile("cp.async.cg.shared.global [%0], [%1], 16;" :: "r"(dst), "l"(src));
}
__device__ __forceinline__ void mma1688(float* c, const uint32_t* a, const uint32_t* b) {
    asm volatile(
        "mma.sync.aligned.m16n8k8.row.col.f32.tf32.tf32.f32 "
        "{%0,%1,%2,%3}, {%4,%5,%6,%7}, {%8,%9}, {%0,%1,%2,%3};"
        : "+f"(c[0]), "+f"(c[1]), "+f"(c[2]), "+f"(c[3])
        : "r"(a[0]), "r"(a[1]), "r"(a[2]), "r"(a[3]), "r"(b[0]), "r"(b[1]));
}
__device__ __forceinline__ void st2_wt(float* p, float x, float y) {
    asm volatile("st.global.wt.v2.f32 [%0], {%1,%2};" :: "l"(p), "f"(x), "f"(y) : "memory");
}

// ---------------------------------------------------------------------------
// tf32 mma.sync GEMM: C[M,N] = A[M,K] @ B[K,N], row-major, K%32==0.
// CTA tile 128x128, BK=32, 3-stage cp.async pipeline, 8 warps at 64x32.
// grid = (M/128, N/128), block = 256.
// ---------------------------------------------------------------------------
#define BM 128
#define BN 128
#define BK 32
#define AST 36            // A smem row stride (floats), conflict-free 4g+t
#define BST 136           // B smem row stride (floats), conflict-free 8t+g
#define A_BYTES (BM*AST*4)            // 18432
#define B_BYTES (BK*BST*4)            // 17408
#define STAGE_BYTES (A_BYTES + B_BYTES)   // 35840
#define MMS_SMEM (3*STAGE_BYTES)          // 107520

__global__ void __launch_bounds__(256) mm_tf32s(const float* __restrict__ A,
                                                const float* __restrict__ B,
                                                float* __restrict__ C,
                                                int Ngl, int K) {
    extern __shared__ float sm[];
    const uint32_t sb = smem_u32(sm);
    const int tid = threadIdx.x;
    const int wid = tid >> 5, lane = tid & 31;
    const int wm = wid >> 2, wn = wid & 3;
    const int g = lane >> 2, t = lane & 3;
    const int m0 = blockIdx.x * BM, n0 = blockIdx.y * BN;
    const float* Ag = A + (size_t)m0 * K;
    const float* Bg = B + n0;
    const int KT = K / BK;

    float acc[4][4][4];
#pragma unroll
    for (int i = 0; i < 4; i++)
#pragma unroll
        for (int j = 0; j < 4; j++)
#pragma unroll
            for (int q = 0; q < 4; q++) acc[i][j][q] = 0.f;

    auto load_stage = [&](int st, int kt) {
        uint32_t sA = sb + st * STAGE_BYTES;
        uint32_t sB = sA + A_BYTES;
#pragma unroll
        for (int l = 0; l < 4; l++) {           // A: 128 rows x 8 chunks
            int c = tid + l * 256;
            int r = c >> 3, kc = c & 7;
            cp16(sA + r * (AST * 4) + kc * 16, Ag + (size_t)r * K + kt * BK + kc * 4);
        }
#pragma unroll
        for (int l = 0; l < 4; l++) {           // B: 32 rows x 32 chunks
            int c = tid + l * 256;
            int r = c >> 5, nc = c & 31;
            cp16(sB + r * (BST * 4) + nc * 16, Bg + (size_t)(kt * BK + r) * Ngl + nc * 4);
        }
    };

    load_stage(0, 0);
    asm volatile("cp.async.commit_group;" ::: "memory");
    load_stage(1, 1);
    asm volatile("cp.async.commit_group;" ::: "memory");

    for (int kt = 0; kt < KT; kt++) {
        const int st = kt % 3;
        asm volatile("cp.async.wait_group 1;" ::: "memory");
        __syncthreads();

        if (kt + 2 < KT) load_stage((kt + 2) % 3, kt + 2);
        asm volatile("cp.async.commit_group;" ::: "memory");

        const float* as = sm + st * (STAGE_BYTES / 4);
        const float* bs = as + A_BYTES / 4;
#pragma unroll
        for (int ks = 0; ks < 4; ks++) {
            const int k0 = ks * 8;
            uint32_t af[4][4], bf[4][2];
#pragma unroll
            for (int mt = 0; mt < 4; mt++) {
                int r0 = (wm * 64 + mt * 16 + g) * AST + k0 + t;
                af[mt][0] = __float_as_uint(as[r0]);
                af[mt][1] = __float_as_uint(as[r0 + 8 * AST]);
                af[mt][2] = __float_as_uint(as[r0 + 4]);
                af[mt][3] = __float_as_uint(as[r0 + 8 * AST + 4]);
            }
#pragma unroll
            for (int nt = 0; nt < 4; nt++) {
                int c0 = (k0 + t) * BST + wn * 32 + nt * 8 + g;
                bf[nt][0] = __float_as_uint(bs[c0]);
                bf[nt][1] = __float_as_uint(bs[c0 + 4 * BST]);
            }
#pragma unroll
            for (int mt = 0; mt < 4; mt++)
#pragma unroll
                for (int nt = 0; nt < 4; nt++)
                    mma1688(acc[mt][nt], af[mt], bf[nt]);
        }
        __syncthreads();
    }

    // Epilogue (streaming stores: written once, consumed by a later kernel)
#pragma unroll
    for (int mt = 0; mt < 4; mt++) {
#pragma unroll
        for (int nt = 0; nt < 4; nt++) {
            int row = m0 + wm * 64 + mt * 16 + g;
            int col = n0 + wn * 32 + nt * 8 + t * 2;
            st2_wt(&C[(size_t)row * Ngl + col], acc[mt][nt][0], acc[mt][nt][1]);
            st2_wt(&C[(size_t)(row + 8) * Ngl + col], acc[mt][nt][2], acc[mt][nt][3]);
        }
    }
}

// ---------------------------------------------------------------------------
// Elementwise tf32 round (vectorized)
// ---------------------------------------------------------------------------
__global__ void __launch_bounds__(256) round_x(float* __restrict__ dst,
                                               const float* __restrict__ src, int n4) {
    int i = blockIdx.x * blockDim.x + threadIdx.x;
    if (i >= n4) return;
    float4 v = ((const float4*)src)[i];
    v.x = round_tf32(v.x); v.y = round_tf32(v.y);
    v.z = round_tf32(v.z); v.w = round_tf32(v.w);
    ((float4*)dst)[i] = v;
}

// ---------------------------------------------------------------------------
// RoPE in-place on g_Q (16 heads) and g_K (4 kv heads).
// ---------------------------------------------------------------------------
__global__ void __launch_bounds__(256) rope_kernel(const int* __restrict__ pos_ids) {
    __shared__ double invs[64];
    if (threadIdx.x < 64)
        invs[threadIdx.x] = exp2(-(double)threadIdx.x * (13.287712379549449 / 64.0));
    __syncthreads();

    int gwarp = (blockIdx.x * blockDim.x + threadIdx.x) >> 5;
    int lane  = threadIdx.x & 31;
    if (gwarp >= ROWS * (NHEADS + NKVH)) return;
    int h   = gwarp % (NHEADS + NKVH);
    int row = gwarp / (NHEADS + NKVH);
    float* p = (h < NHEADS) ? (g_Q + (size_t)row * HID + h * HDIM)
                            : (g_K + (size_t)row * (NKVH * HDIM) + (h - NHEADS) * HDIM);
    int ps = pos_ids[row];
    const double TWO_PI  = 6.283185307179586;
    const double INV_2PI = 0.15915494309189535;
#pragma unroll
    for (int jj = 0; jj < 2; jj++) {
        int j = lane + jj * 32;
        double ang = (double)ps * invs[j];
        ang -= floor(ang * INV_2PI) * TWO_PI;
        float s, c;
        sincosf((float)ang, &s, &c);
        float x0 = p[j], x1 = p[j + 64];
        p[j]      = x0 * c - x1 * s;
        p[j + 64] = x1 * c + x0 * s;
    }
}

// ---------------------------------------------------------------------------
// Flash-style grouped causal attention, fp32; epilogue rounds context to tf32
// so the O-proj tensor GEMM sees pre-rounded input.
// ---------------------------------------------------------------------------
#define ATT_SMEM ((64*128 + 64*132 + 64*128 + 64*64) * 4)   // 115712 bytes

__global__ void __launch_bounds__(256) attn_kernel() {
    extern __shared__ float smf[];
    float* Qs = smf;                // [64][128]
    float* Ks = Qs + 64 * 128;      // [64][132] padded
    float* Vs = Ks + 64 * 132;      // [64][128]
    float* Ps = Vs + 64 * 128;      // [64][64]

    const int qt = blockIdx.x;
    const int h  = blockIdx.y;
    const int gi = blockIdx.z;
    const int b = gi >> 2, grp = gi & 3;
    const int kvh = h >> 2;
    const int shift = (h >= NHEADS / 2) ? (GRPSZ / 2) : 0;
    const int base = grp * GRPSZ + shift;
    const int tid = threadIdx.x, tx = tid & 15, ty = tid >> 4;

#pragma unroll
    for (int l = 0; l < 8; l++) {
        int fid = tid + l * 256;
        int r = fid >> 5, d4 = (fid & 31) * 4;
        int srow = b * SEQ + ((base + qt * 64 + r) & (SEQ - 1));
        *(float4*)&Qs[r * 128 + d4] = *(const float4*)&g_Q[(size_t)srow * HID + h * HDIM + d4];
    }

    float m[4], lsum[4], O[4][8];
#pragma unroll
    for (int r = 0; r < 4; r++) {
        m[r] = -1e30f; lsum[r] = 0.f;
#pragma unroll
        for (int c = 0; c < 8; c++) O[r][c] = 0.f;
    }

    const float SC = 0.08838834764831845f;
    const unsigned FULL = 0xffffffffu;

    for (int kt = 0; kt <= qt; kt++) {
#pragma unroll
        for (int l = 0; l < 8; l++) {
            int fid = tid + l * 256;
            int r = fid >> 5, d4 = (fid & 31) * 4;
            int srow = b * SEQ + ((base + kt * 64 + r) & (SEQ - 1));
            size_t off = (size_t)srow * (NKVH * HDIM) + kvh * HDIM + d4;
            *(float4*)&Ks[r * 132 + d4] = *(const float4*)&g_K[off];
            *(float4*)&Vs[r * 128 + d4] = *(const float4*)&g_V[off];
        }
        __syncthreads();

        float s[4][4];
#pragma unroll
        for (int r = 0; r < 4; r++)
#pragma unroll
            for (int c = 0; c < 4; c++) s[r][c] = 0.f;

#pragma unroll 8
        for (int k4 = 0; k4 < 32; k4++) {
            float4 qv[4], kv[4];
#pragma unroll
            for (int r = 0; r < 4; r++)
                qv[r] = *(const float4*)&Qs[(ty * 4 + r) * 128 + k4 * 4];
#pragma unroll
            for (int c = 0; c < 4; c++)
                kv[c] = *(const float4*)&Ks[(tx + 16 * c) * 132 + k4 * 4];
#pragma unroll
            for (int r = 0; r < 4; r++)
#pragma unroll
                for (int c = 0; c < 4; c++) {
                    s[r][c] = fmaf(qv[r].x, kv[c].x, s[r][c]);
                    s[r][c] = fmaf(qv[r].y, kv[c].y, s[r][c]);
                    s[r][c] = fmaf(qv[r].z, kv[c].z, s[r][c]);
                    s[r][c] = fmaf(qv[r].w, kv[c].w, s[r][c]);
                }
        }

        const bool diag = (kt == qt);
#pragma unroll
        for (int r = 0; r < 4; r++) {
#pragma unroll
            for (int c = 0; c < 4; c++) {
                float sv = s[r][c] * SC;
                if (diag && (tx + 16 * c) > (ty * 4 + r)) sv = -1e30f;
                s[r][c] = sv;
            }
            float mx = fmaxf(fmaxf(s[r][0], s[r][1]), fmaxf(s[r][2], s[r][3]));
#pragma unroll
            for (int o = 1; o < 16; o <<= 1)
                mx = fmaxf(mx, __shfl_xor_sync(FULL, mx, o));
            float mnew = fmaxf(m[r], mx);
            float corr = __expf(m[r] - mnew);
            float psum = 0.f;
#pragma unroll
            for (int c = 0; c < 4; c++) {
                float p = __expf(s[r][c] - mnew);
                Ps[(ty * 4 + r) * 64 + tx + 16 * c] = p;
                psum += p;
            }
#pragma unroll
            for (int o = 1; o < 16; o <<= 1)
                psum += __shfl_xor_sync(FULL, psum, o);
            lsum[r] = lsum[r] * corr + psum;
            m[r] = mnew;
#pragma unroll
            for (int c = 0; c < 8; c++) O[r][c] *= corr;
        }
        __syncwarp();

#pragma unroll 4
        for (int k = 0; k < 64; k++) {
            float4 v0 = *(const float4*)&Vs[k * 128 + tx * 8];
            float4 v1 = *(const float4*)&Vs[k * 128 + tx * 8 + 4];
#pragma unroll
            for (int r = 0; r < 4; r++) {
                float p = Ps[(ty * 4 + r) * 64 + k];
                O[r][0] = fmaf(p, v0.x, O[r][0]);
                O[r][1] = fmaf(p, v0.y, O[r][1]);
                O[r][2] = fmaf(p, v0.z, O[r][2]);
                O[r][3] = fmaf(p, v0.w, O[r][3]);
                O[r][4] = fmaf(p, v1.x, O[r][4]);
                O[r][5] = fmaf(p, v1.y, O[r][5]);
                O[r][6] = fmaf(p, v1.z, O[r][6]);
                O[r][7] = fmaf(p, v1.w, O[r][7]);
            }
        }
        __syncthreads();
    }

#pragma unroll
    for (int r = 0; r < 4; r++) {
        float inv = 1.f / lsum[r];
        int t = qt * 64 + ty * 4 + r;
        int srow = b * SEQ + ((base + t) & (SEQ - 1));
        float* o = &g_C[(size_t)srow * HID + h * HDIM + tx * 8];
        *(float4*)o = make_float4(round_tf32(O[r][0] * inv), round_tf32(O[r][1] * inv),
                                  round_tf32(O[r][2] * inv), round_tf32(O[r][3] * inv));
        *(float4*)(o + 4) = make_float4(round_tf32(O[r][4] * inv), round_tf32(O[r][5] * inv),
                                        round_tf32(O[r][6] * inv), round_tf32(O[r][7] * inv));
    }
}

// ---------------------------------------------------------------------------
extern "C" void kernel_launch(void* const* d_in, const int* in_sizes, int n_in,
                              void* d_out, int out_size) {
    const float* X   = (const float*)d_in[0];
    const int*   pos = (const int*)d_in[2];
    const float* Wq  = (const float*)d_in[3];   // (2048, 2048) [K,N]
    const float* Wk  = (const float*)d_in[4];   // (2048, 512)
    const float* Wv  = (const float*)d_in[5];   // (2048, 512)
    const float* Wo  = (const float*)d_in[6];   // (2048, 2048)
    float* out = (float*)d_out;

    float *Qb, *Kb, *Vb, *Cb, *Xr, *Wqr, *Wkr, *Wvr, *Wor;
    cudaGetSymbolAddress((void**)&Qb, g_Q);
    cudaGetSymbolAddress((void**)&Kb, g_K);
    cudaGetSymbolAddress((void**)&Vb, g_V);
    cudaGetSymbolAddress((void**)&Cb, g_C);
    cudaGetSymbolAddress((void**)&Xr, g_Xr);
    cudaGetSymbolAddress((void**)&Wqr, g_Wq);
    cudaGetSymbolAddress((void**)&Wkr, g_Wk);
    cudaGetSymbolAddress((void**)&Wvr, g_Wv);
    cudaGetSymbolAddress((void**)&Wor, g_Wo);

    cudaFuncSetAttribute(attn_kernel, cudaFuncAttributeMaxDynamicSharedMemorySize, ATT_SMEM);
    cudaFuncSetAttribute(mm_tf32s, cudaFuncAttributeMaxDynamicSharedMemorySize, MMS_SMEM);

    // Prep: tf32-round X and weights (layouts unchanged)
    round_x<<<(ROWS * HID / 4 + 255) / 256, 256>>>(Xr, X, ROWS * HID / 4);
    round_x<<<(HID * HID / 4 + 255) / 256, 256>>>(Wqr, Wq, HID * HID / 4);
    round_x<<<(HID * NKVH * HDIM / 4 + 255) / 256, 256>>>(Wkr, Wk, HID * NKVH * HDIM / 4);
    round_x<<<(HID * NKVH * HDIM / 4 + 255) / 256, 256>>>(Wvr, Wv, HID * NKVH * HDIM / 4);
    round_x<<<(HID * HID / 4 + 255) / 256, 256>>>(Wor, Wo, HID * HID / 4);

    // QKV projections (tf32 mma.sync)
    mm_tf32s<<<dim3(ROWS / 128, HID / 128), 256, MMS_SMEM>>>(Xr, Wqr, Qb, HID, HID);
    mm_tf32s<<<dim3(ROWS / 128, (NKVH * HDIM) / 128), 256, MMS_SMEM>>>(Xr, Wkr, Kb, NKVH * HDIM, HID);
    mm_tf32s<<<dim3(ROWS / 128, (NKVH * HDIM) / 128), 256, MMS_SMEM>>>(Xr, Wvr, Vb, NKVH * HDIM, HID);

    // RoPE on Q and K
    rope_kernel<<<20480, 256>>>(pos);

    // Grouped shifted causal attention (fp32)
    attn_kernel<<<dim3(16, 16, 8), 256, ATT_SMEM>>>();

    // Output projection (tf32 mma.sync)
    mm_tf32s<<<dim3(ROWS / 128, HID / 128), 256, MMS_SMEM>>>(Cb, Wor, out, HID, HID);
}

// round 11
// speedup vs baseline: 3.0529x; 1.4842x over previous
#include <cuda_runtime.h>
#include <math.h>
#include <stdint.h>

// Problem constants
#define SEQ   4096
#define BATCH 2
#define HID   2048
#define NHEADS 16
#define NKVH   4
#define HDIM   128
#define ROWS  (BATCH*SEQ)          // 8192
#define GRPSZ 1024
#define NGRP  4

// Scratch (no cudaMalloc allowed)
__device__ float g_Q[ROWS*HID];            // 64MB
__device__ float g_K[ROWS*NKVH*HDIM];      // 16MB
__device__ float g_V[ROWS*NKVH*HDIM];      // 16MB
__device__ float g_C[ROWS*HID];            // 64MB attention context (tf32-rounded)
__device__ float g_Xr[ROWS*HID];           // 64MB tf32-rounded hidden states
__device__ float g_Wq[HID*HID];            // rounded weights, original [K,N] layout
__device__ float g_Wk[HID*(NKVH*HDIM)];
__device__ float g_Wv[HID*(NKVH*HDIM)];
__device__ float g_Wo[HID*HID];

// ---------------------------------------------------------------------------
// Helpers
// ---------------------------------------------------------------------------
__device__ __forceinline__ uint32_t smem_u32(const void* p) {
    uint32_t a;
    asm("{ .reg .u64 t; cvta.to.shared.u64 t, %1; cvt.u32.u64 %0, t; }" : "=r"(a) : "l"(p));
    return a;
}
__device__ __forceinline__ float round_tf32(float x) {
    uint32_t u;
    asm("cvt.rna.tf32.f32 %0, %1;" : "=r"(u) : "f"(x));
    return __uint_as_float(u);
}
__device__ __forceinline__ void cp16(uint32_t dst, const void* src) {
    asm volatile("cp.async.cg.shared.global [%0], [%1], 16;" :: "r"(dst), "l"(src));
}
__device__ __forceinline__ void mma1688(float* c, const uint32_t* a, const uint32_t* b) {
    asm volatile(
        "mma.sync.aligned.m16n8k8.row.col.f32.tf32.tf32.f32 "
        "{%0,%1,%2,%3}, {%4,%5,%6,%7}, {%8,%9}, {%0,%1,%2,%3};"
        : "+f"(c[0]), "+f"(c[1]), "+f"(c[2]), "+f"(c[3])
        : "r"(a[0]), "r"(a[1]), "r"(a[2]), "r"(a[3]), "r"(b[0]), "r"(b[1]));
}
__device__ __forceinline__ void st2_wt(float* p, float x, float y) {
    asm volatile("st.global.wt.v2.f32 [%0], {%1,%2};" :: "l"(p), "f"(x), "f"(y) : "memory");
}

// ---------------------------------------------------------------------------
// tf32 mma.sync GEMM: C[M,N] = A[M,K] @ B[K,N], row-major, K%32==0.
// CTA tile 128x128, BK=32, 3-stage cp.async pipeline, 8 warps at 64x32.
// ---------------------------------------------------------------------------
#define BM 128
#define BN 128
#define BK 32
#define AST 36
#define BST 136
#define A_BYTES (BM*AST*4)
#define B_BYTES (BK*BST*4)
#define STAGE_BYTES (A_BYTES + B_BYTES)
#define MMS_SMEM (3*STAGE_BYTES)          // 107520

__global__ void __launch_bounds__(256) mm_tf32s(const float* __restrict__ A,
                                                const float* __restrict__ B,
                                                float* __restrict__ C,
                                                int Ngl, int K) {
    extern __shared__ float sm[];
    const uint32_t sb = smem_u32(sm);
    const int tid = threadIdx.x;
    const int wid = tid >> 5, lane = tid & 31;
    const int wm = wid >> 2, wn = wid & 3;
    const int g = lane >> 2, t = lane & 3;
    const int m0 = blockIdx.x * BM, n0 = blockIdx.y * BN;
    const float* Ag = A + (size_t)m0 * K;
    const float* Bg = B + n0;
    const int KT = K / BK;

    float acc[4][4][4];
#pragma unroll
    for (int i = 0; i < 4; i++)
#pragma unroll
        for (int j = 0; j < 4; j++)
#pragma unroll
            for (int q = 0; q < 4; q++) acc[i][j][q] = 0.f;

    auto load_stage = [&](int st, int kt) {
        uint32_t sA = sb + st * STAGE_BYTES;
        uint32_t sB = sA + A_BYTES;
#pragma unroll
        for (int l = 0; l < 4; l++) {
            int c = tid + l * 256;
            int r = c >> 3, kc = c & 7;
            cp16(sA + r * (AST * 4) + kc * 16, Ag + (size_t)r * K + kt * BK + kc * 4);
        }
#pragma unroll
        for (int l = 0; l < 4; l++) {
            int c = tid + l * 256;
            int r = c >> 5, nc = c & 31;
            cp16(sB + r * (BST * 4) + nc * 16, Bg + (size_t)(kt * BK + r) * Ngl + nc * 4);
        }
    };

    load_stage(0, 0);
    asm volatile("cp.async.commit_group;" ::: "memory");
    load_stage(1, 1);
    asm volatile("cp.async.commit_group;" ::: "memory");

    for (int kt = 0; kt < KT; kt++) {
        const int st = kt % 3;
        asm volatile("cp.async.wait_group 1;" ::: "memory");
        __syncthreads();

        if (kt + 2 < KT) load_stage((kt + 2) % 3, kt + 2);
        asm volatile("cp.async.commit_group;" ::: "memory");

        const float* as = sm + st * (STAGE_BYTES / 4);
        const float* bs = as + A_BYTES / 4;
#pragma unroll
        for (int ks = 0; ks < 4; ks++) {
            const int k0 = ks * 8;
            uint32_t af[4][4], bf[4][2];
#pragma unroll
            for (int mt = 0; mt < 4; mt++) {
                int r0 = (wm * 64 + mt * 16 + g) * AST + k0 + t;
                af[mt][0] = __float_as_uint(as[r0]);
                af[mt][1] = __float_as_uint(as[r0 + 8 * AST]);
                af[mt][2] = __float_as_uint(as[r0 + 4]);
                af[mt][3] = __float_as_uint(as[r0 + 8 * AST + 4]);
            }
#pragma unroll
            for (int nt = 0; nt < 4; nt++) {
                int c0 = (k0 + t) * BST + wn * 32 + nt * 8 + g;
                bf[nt][0] = __float_as_uint(bs[c0]);
                bf[nt][1] = __float_as_uint(bs[c0 + 4 * BST]);
            }
#pragma unroll
            for (int mt = 0; mt < 4; mt++)
#pragma unroll
                for (int nt = 0; nt < 4; nt++)
                    mma1688(acc[mt][nt], af[mt], bf[nt]);
        }
        __syncthreads();
    }

#pragma unroll
    for (int mt = 0; mt < 4; mt++) {
#pragma unroll
        for (int nt = 0; nt < 4; nt++) {
            int row = m0 + wm * 64 + mt * 16 + g;
            int col = n0 + wn * 32 + nt * 8 + t * 2;
            st2_wt(&C[(size_t)row * Ngl + col], acc[mt][nt][0], acc[mt][nt][1]);
            st2_wt(&C[(size_t)(row + 8) * Ngl + col], acc[mt][nt][2], acc[mt][nt][3]);
        }
    }
}

// ---------------------------------------------------------------------------
// Elementwise tf32 round (vectorized)
// ---------------------------------------------------------------------------
__global__ void __launch_bounds__(256) round_x(float* __restrict__ dst,
                                               const float* __restrict__ src, int n4) {
    int i = blockIdx.x * blockDim.x + threadIdx.x;
    if (i >= n4) return;
    float4 v = ((const float4*)src)[i];
    v.x = round_tf32(v.x); v.y = round_tf32(v.y);
    v.z = round_tf32(v.z); v.w = round_tf32(v.w);
    ((float4*)dst)[i] = v;
}

// ---------------------------------------------------------------------------
// RoPE in-place on g_Q (16 heads, folds 1/sqrt(HD) scale) and g_K (4 kv heads).
// Outputs rounded to tf32 so the attention MMAs see exact tf32 operands.
// ---------------------------------------------------------------------------
#define ATT_SCALE 0.08838834764831845f

__global__ void __launch_bounds__(256) rope_kernel(const int* __restrict__ pos_ids) {
    __shared__ double invs[64];
    if (threadIdx.x < 64)
        invs[threadIdx.x] = exp2(-(double)threadIdx.x * (13.287712379549449 / 64.0));
    __syncthreads();

    int gwarp = (blockIdx.x * blockDim.x + threadIdx.x) >> 5;
    int lane  = threadIdx.x & 31;
    if (gwarp >= ROWS * (NHEADS + NKVH)) return;
    int h   = gwarp % (NHEADS + NKVH);
    int row = gwarp / (NHEADS + NKVH);
    bool isq = (h < NHEADS);
    float* p = isq ? (g_Q + (size_t)row * HID + h * HDIM)
                   : (g_K + (size_t)row * (NKVH * HDIM) + (h - NHEADS) * HDIM);
    int ps = pos_ids[row];
    const double TWO_PI  = 6.283185307179586;
    const double INV_2PI = 0.15915494309189535;
    const float sc = isq ? ATT_SCALE : 1.0f;
#pragma unroll
    for (int jj = 0; jj < 2; jj++) {
        int j = lane + jj * 32;
        double ang = (double)ps * invs[j];
        ang -= floor(ang * INV_2PI) * TWO_PI;
        float s, c;
        sincosf((float)ang, &s, &c);
        float x0 = p[j], x1 = p[j + 64];
        p[j]      = round_tf32((x0 * c - x1 * s) * sc);
        p[j + 64] = round_tf32((x1 * c + x0 * s) * sc);
    }
}

// ---------------------------------------------------------------------------
// Flash attention with tf32 mma.sync.
// CTA: 64 q-rows x 1 head x 1 group. 128 threads / 4 warps, 16 q-rows/warp.
// Q fragments register-resident (loop invariant); K/V/P in smem.
// grid = (16 qtiles, 16 heads, 8 groups). Long CTAs first (qt descending).
// ---------------------------------------------------------------------------
#define KSTRIDE 132      // bank = 4g+t (conflict-free for K frags / Q frags)
#define VSTRIDE 136      // bank = 8t+g (bijective, conflict-free for V frags)
#define PSTRIDE 68       // bank = 4g+t (conflict-free for P frags)
#define ATT2_SMEM ((64*KSTRIDE + 64*VSTRIDE + 64*PSTRIDE) * 4)   // 86016 bytes

__global__ void __launch_bounds__(128, 2) attn_mma() {
    extern __shared__ float smf[];
    float* Ks = smf;                       // [64][132]; also Q staging in prologue
    float* Vs = Ks + 64 * KSTRIDE;         // [64][136]
    float* Ps = Vs + 64 * VSTRIDE;         // [64][68]

    const int qt = 15 - blockIdx.x;        // descending work for load balance
    const int h  = blockIdx.y;
    const int gi = blockIdx.z;
    const int b = gi >> 2, grp = gi & 3;
    const int kvh = h >> 2;
    const int shift = (h >= NHEADS / 2) ? (GRPSZ / 2) : 0;
    const int base = grp * GRPSZ + shift;
    const int tid = threadIdx.x, wid = tid >> 5, lane = tid & 31;
    const int g = lane >> 2, t = lane & 3;
    const int wr = wid * 16;               // warp's first q-row (local)

    // ---- Prologue: stage Q tile through Ks, lift fragments to registers ----
#pragma unroll
    for (int l = 0; l < 16; l++) {
        int fid = tid + l * 128;
        int r = fid >> 5, d4 = (fid & 31) * 4;
        int srow = b * SEQ + ((base + qt * 64 + r) & (SEQ - 1));
        *(float4*)&Ks[r * KSTRIDE + d4] = *(const float4*)&g_Q[(size_t)srow * HID + h * HDIM + d4];
    }
    __syncthreads();
    uint32_t qf[16][4];
#pragma unroll
    for (int ks = 0; ks < 16; ks++) {
        int k0 = ks * 8;
        qf[ks][0] = __float_as_uint(Ks[(wr + g) * KSTRIDE + k0 + t]);
        qf[ks][1] = __float_as_uint(Ks[(wr + g + 8) * KSTRIDE + k0 + t]);
        qf[ks][2] = __float_as_uint(Ks[(wr + g) * KSTRIDE + k0 + t + 4]);
        qf[ks][3] = __float_as_uint(Ks[(wr + g + 8) * KSTRIDE + k0 + t + 4]);
    }
    __syncthreads();

    // ---- State ----
    float oacc[16][4];
#pragma unroll
    for (int nt = 0; nt < 16; nt++)
#pragma unroll
        for (int q = 0; q < 4; q++) oacc[nt][q] = 0.f;
    float m0 = -1e30f, m1 = -1e30f, l0 = 0.f, l1 = 0.f;
    const int row0 = qt * 64 + wr + g;     // global (in-group) q index, row g
    const int row1 = row0 + 8;
    const unsigned FULL = 0xffffffffu;

    for (int kt = 0; kt <= qt; kt++) {
        // ---- Load K/V tiles ----
#pragma unroll
        for (int l = 0; l < 16; l++) {
            int fid = tid + l * 128;
            int r = fid >> 5, d4 = (fid & 31) * 4;
            int srow = b * SEQ + ((base + kt * 64 + r) & (SEQ - 1));
            size_t off = (size_t)srow * (NKVH * HDIM) + kvh * HDIM + d4;
            *(float4*)&Ks[r * KSTRIDE + d4] = *(const float4*)&g_K[off];
            *(float4*)&Vs[r * VSTRIDE + d4] = *(const float4*)&g_V[off];
        }
        __syncthreads();

        // ---- S = (Q*scale) K^T : warp strip 16 x 64 ----
        float sa[8][4];
#pragma unroll
        for (int nt = 0; nt < 8; nt++) {
#pragma unroll
            for (int q = 0; q < 4; q++) sa[nt][q] = 0.f;
            const int c0 = nt * 8 + g;
#pragma unroll
            for (int ks = 0; ks < 16; ks++) {
                uint32_t bf[2];
                bf[0] = __float_as_uint(Ks[c0 * KSTRIDE + ks * 8 + t]);
                bf[1] = __float_as_uint(Ks[c0 * KSTRIDE + ks * 8 + t + 4]);
                mma1688(sa[nt], qf[ks], bf);
            }
        }

        // ---- Online softmax ----
        const bool diag = (kt == qt);
        float mx0 = -1e30f, mx1 = -1e30f;
#pragma unroll
        for (int nt = 0; nt < 8; nt++) {
            if (diag) {
                int col = kt * 64 + nt * 8 + 2 * t;
                if (col > row0)     sa[nt][0] = -1e30f;
                if (col + 1 > row0) sa[nt][1] = -1e30f;
                if (col > row1)     sa[nt][2] = -1e30f;
                if (col + 1 > row1) sa[nt][3] = -1e30f;
            }
            mx0 = fmaxf(mx0, fmaxf(sa[nt][0], sa[nt][1]));
            mx1 = fmaxf(mx1, fmaxf(sa[nt][2], sa[nt][3]));
        }
        mx0 = fmaxf(mx0, __shfl_xor_sync(FULL, mx0, 1));
        mx0 = fmaxf(mx0, __shfl_xor_sync(FULL, mx0, 2));
        mx1 = fmaxf(mx1, __shfl_xor_sync(FULL, mx1, 1));
        mx1 = fmaxf(mx1, __shfl_xor_sync(FULL, mx1, 2));
        float mn0 = fmaxf(m0, mx0), mn1 = fmaxf(m1, mx1);
        float cr0 = __expf(m0 - mn0), cr1 = __expf(m1 - mn1);
        m0 = mn0; m1 = mn1;

        float ps0 = 0.f, ps1 = 0.f;
#pragma unroll
        for (int nt = 0; nt < 8; nt++) {
            float p0 = __expf(sa[nt][0] - m0), p1 = __expf(sa[nt][1] - m0);
            float p2 = __expf(sa[nt][2] - m1), p3 = __expf(sa[nt][3] - m1);
            ps0 += p0 + p1; ps1 += p2 + p3;
            int cw = nt * 8 + 2 * t;
            *(float2*)&Ps[(wr + g) * PSTRIDE + cw]     = make_float2(round_tf32(p0), round_tf32(p1));
            *(float2*)&Ps[(wr + g + 8) * PSTRIDE + cw] = make_float2(round_tf32(p2), round_tf32(p3));
        }
        ps0 += __shfl_xor_sync(FULL, ps0, 1);
        ps0 += __shfl_xor_sync(FULL, ps0, 2);
        ps1 += __shfl_xor_sync(FULL, ps1, 1);
        ps1 += __shfl_xor_sync(FULL, ps1, 2);
        l0 = l0 * cr0 + ps0; l1 = l1 * cr1 + ps1;
#pragma unroll
        for (int nt = 0; nt < 16; nt++) {
            oacc[nt][0] *= cr0; oacc[nt][1] *= cr0;
            oacc[nt][2] *= cr1; oacc[nt][3] *= cr1;
        }
        __syncwarp();

        // ---- O += P V : warp strip 16 x 128 ----
#pragma unroll
        for (int ks = 0; ks < 8; ks++) {
            uint32_t pf[4];
            int k0 = ks * 8;
            pf[0] = __float_as_uint(Ps[(wr + g) * PSTRIDE + k0 + t]);
            pf[1] = __float_as_uint(Ps[(wr + g + 8) * PSTRIDE + k0 + t]);
            pf[2] = __float_as_uint(Ps[(wr + g) * PSTRIDE + k0 + t + 4]);
            pf[3] = __float_as_uint(Ps[(wr + g + 8) * PSTRIDE + k0 + t + 4]);
#pragma unroll
            for (int nt = 0; nt < 16; nt++) {
                uint32_t bf[2];
                bf[0] = __float_as_uint(Vs[(k0 + t) * VSTRIDE + nt * 8 + g]);
                bf[1] = __float_as_uint(Vs[(k0 + t + 4) * VSTRIDE + nt * 8 + g]);
                mma1688(oacc[nt], pf, bf);
            }
        }
        __syncthreads();
    }

    // ---- Epilogue: normalize, tf32-round, write unshifted ----
    float inv0 = 1.f / l0, inv1 = 1.f / l1;
    int srow0 = b * SEQ + ((base + row0) & (SEQ - 1));
    int srow1 = b * SEQ + ((base + row1) & (SEQ - 1));
    float* o0 = &g_C[(size_t)srow0 * HID + h * HDIM];
    float* o1 = &g_C[(size_t)srow1 * HID + h * HDIM];
#pragma unroll
    for (int nt = 0; nt < 16; nt++) {
        int col = nt * 8 + 2 * t;
        *(float2*)&o0[col] = make_float2(round_tf32(oacc[nt][0] * inv0),
                                         round_tf32(oacc[nt][1] * inv0));
        *(float2*)&o1[col] = make_float2(round_tf32(oacc[nt][2] * inv1),
                                         round_tf32(oacc[nt][3] * inv1));
    }
}

// ---------------------------------------------------------------------------
extern "C" void kernel_launch(void* const* d_in, const int* in_sizes, int n_in,
                              void* d_out, int out_size) {
    const float* X   = (const float*)d_in[0];
    const int*   pos = (const int*)d_in[2];
    const float* Wq  = (const float*)d_in[3];   // (2048, 2048) [K,N]
    const float* Wk  = (const float*)d_in[4];   // (2048, 512)
    const float* Wv  = (const float*)d_in[5];   // (2048, 512)
    const float* Wo  = (const float*)d_in[6];   // (2048, 2048)
    float* out = (float*)d_out;

    float *Qb, *Kb, *Vb, *Cb, *Xr, *Wqr, *Wkr, *Wvr, *Wor;
    cudaGetSymbolAddress((void**)&Qb, g_Q);
    cudaGetSymbolAddress((void**)&Kb, g_K);
    cudaGetSymbolAddress((void**)&Vb, g_V);
    cudaGetSymbolAddress((void**)&Cb, g_C);
    cudaGetSymbolAddress((void**)&Xr, g_Xr);
    cudaGetSymbolAddress((void**)&Wqr, g_Wq);
    cudaGetSymbolAddress((void**)&Wkr, g_Wk);
    cudaGetSymbolAddress((void**)&Wvr, g_Wv);
    cudaGetSymbolAddress((void**)&Wor, g_Wo);

    cudaFuncSetAttribute(attn_mma, cudaFuncAttributeMaxDynamicSharedMemorySize, ATT2_SMEM);
    cudaFuncSetAttribute(mm_tf32s, cudaFuncAttributeMaxDynamicSharedMemorySize, MMS_SMEM);

    // Prep: tf32-round X and weights (layouts unchanged)
    round_x<<<(ROWS * HID / 4 + 255) / 256, 256>>>(Xr, X, ROWS * HID / 4);
    round_x<<<(HID * HID / 4 + 255) / 256, 256>>>(Wqr, Wq, HID * HID / 4);
    round_x<<<(HID * NKVH * HDIM / 4 + 255) / 256, 256>>>(Wkr, Wk, HID * NKVH * HDIM / 4);
    round_x<<<(HID * NKVH * HDIM / 4 + 255) / 256, 256>>>(Wvr, Wv, HID * NKVH * HDIM / 4);
    round_x<<<(HID * HID / 4 + 255) / 256, 256>>>(Wor, Wo, HID * HID / 4);

    // QKV projections (tf32 mma.sync)
    mm_tf32s<<<dim3(ROWS / 128, HID / 128), 256, MMS_SMEM>>>(Xr, Wqr, Qb, HID, HID);
    mm_tf32s<<<dim3(ROWS / 128, (NKVH * HDIM) / 128), 256, MMS_SMEM>>>(Xr, Wkr, Kb, NKVH * HDIM, HID);
    mm_tf32s<<<dim3(ROWS / 128, (NKVH * HDIM) / 128), 256, MMS_SMEM>>>(Xr, Wvr, Vb, NKVH * HDIM, HID);

    // Round V in place (PV mma B operand)
    round_x<<<(ROWS * NKVH * HDIM / 4 + 255) / 256, 256>>>(Vb, Vb, ROWS * NKVH * HDIM / 4);

    // RoPE on Q (folds 1/sqrt(HD)) and K; outputs tf32-rounded
    rope_kernel<<<20480, 256>>>(pos);

    // Grouped shifted causal attention (tf32 mma.sync)
    attn_mma<<<dim3(16, 16, 8), 128, ATT2_SMEM>>>();

    // Output projection (tf32 mma.sync)
    mm_tf32s<<<dim3(ROWS / 128, HID / 128), 256, MMS_SMEM>>>(Cb, Wor, out, HID, HID);
}